// round 10
// baseline (speedup 1.0000x reference)
#include <cuda_runtime.h>
#include <cuda_bf16.h>
#include <cuda_fp16.h>
#include <cstdint>

#define S    1024
#define CD   64
#define DD   256
#define FD   512
#define BNT  32
#define UK   96      // padded low-rank K (66 -> 96)

// bf16 split operands (bperm layout)
__device__ __align__(256) __nv_bfloat16 g_xth[BNT * S * CD];
__device__ __align__(256) __nv_bfloat16 g_xtl[BNT * S * CD];
__device__ __align__(256) __nv_bfloat16 g_uh [BNT * S * UK];
__device__ __align__(256) __nv_bfloat16 g_ul [BNT * S * UK];
__device__ __align__(256) __nv_bfloat16 g_wh [BNT * S * 128];
__device__ __align__(256) __nv_bfloat16 g_wl [BNT * S * 128];
__device__ __align__(256) __nv_bfloat16 g_gh [128 * UK];
__device__ __align__(256) __nv_bfloat16 g_gl [128 * UK];
__device__ __align__(256) __nv_bfloat16 g_ybh[BNT * S * DD];
__device__ __align__(256) __nv_bfloat16 g_ybl[BNT * S * DD];
__device__ __align__(256) __nv_bfloat16 g_wih[DD * CD];
__device__ __align__(256) __nv_bfloat16 g_wil[DD * CD];
__device__ __align__(256) __nv_bfloat16 g_woh[CD * DD];
__device__ __align__(256) __nv_bfloat16 g_wol[CD * DD];
// fp16 operands (bperm layout)
__device__ __align__(256) __half g_ph  [(long)BNT * S * S];
__device__ __align__(256) __half g_xcs [BNT * CD * S];   // x in [c][s]
__device__ __align__(256) __half g_pxh [BNT * S * CD];   // p.x
__device__ __align__(256) __half g_hnh [BNT * S * DD];
__device__ __align__(256) __half g_hfh [BNT * S * FD];
__device__ __align__(256) __half g_w1h [FD * DD];
__device__ __align__(256) __half g_w2h [DD * FD];
__device__ __align__(256) __half g_wifh[DD * CD];        // W_in fp16 (att rebuild)
// fp32
__device__ __align__(256) float  g_t   [BNT * S * DD];
__device__ __align__(256) float  g_xtf [BNT * S * CD];   // x [s][c] fp32
__device__ __align__(256) float2 g_murs[BNT * S];
__device__ __align__(256) float  g_p   [(long)BNT * S * S];
__device__ __align__(256) float  g_att [BNT * S * DD];

// ---------------------------------------------------------------------------
__device__ __forceinline__ int bperm(int k) {   // 16-bit k-perm within 32
    return (k & ~31) | (((k >> 1) & 3) << 3) | (((k >> 3) & 3) << 1) | (k & 1);
}

#define MMA_BF16(d, a0, a1, a2, a3, b0, b1)                                   \
    asm volatile("mma.sync.aligned.m16n8k16.row.col.f32.bf16.bf16.f32 "       \
                 "{%0,%1,%2,%3}, {%4,%5,%6,%7}, {%8,%9}, {%0,%1,%2,%3};\n"    \
                 : "+f"(d[0]), "+f"(d[1]), "+f"(d[2]), "+f"(d[3])             \
                 : "r"(a0), "r"(a1), "r"(a2), "r"(a3), "r"(b0), "r"(b1))

#define MMA_F16(d, a0, a1, a2, a3, b0, b1)                                    \
    asm volatile("mma.sync.aligned.m16n8k16.row.col.f32.f16.f16.f32 "         \
                 "{%0,%1,%2,%3}, {%4,%5,%6,%7}, {%8,%9}, {%0,%1,%2,%3};\n"    \
                 : "+f"(d[0]), "+f"(d[1]), "+f"(d[2]), "+f"(d[3])             \
                 : "r"(a0), "r"(a1), "r"(a2), "r"(a3), "r"(b0), "r"(b1))

#define UF(x) __float_as_uint(x)

#define CP16(dst, src)                                                        \
    asm volatile("cp.async.cg.shared.global [%0], [%1], 16;\n"                \
                 :: "r"(dst), "l"(src))

__device__ __forceinline__ int sw_addr(int m, int q) {
    return m * 16 + (((q ^ ((m >> 1) & 3)) & 3) << 2);
}

__device__ __forceinline__ void bf16split(float v, __nv_bfloat16& h, __nv_bfloat16& l) {
    h = __float2bfloat16_rn(v);
    l = __float2bfloat16_rn(v - __bfloat162float(h));
}

// ---------------------------------------------------------------------------
// cp.async 3-stage pipelined MMA GEMM (round-8 core).
// MODE 0: fp16 single-pass, BK=64.  MODE 1: bf16 2-term split, BK=32.
// EPI 0: fp32 store        1: relu -> fp16 bperm-col
//     2: +R -> fp32        3: scatter to output layout
//     4: +R -> bf16 hi/lo split bperm-col
//     5: bf16 hi/lo split bperm-col (no residual)
//     6: fp16 bperm-col (no relu)
// CAUSAL 1: tile skip (scores); 2: K limited to m0+128 (px)
// ---------------------------------------------------------------------------
template<int MODE, int EPI, int CAUSAL>
__global__ __launch_bounds__(256, 2)
void mma_gemm(const void* __restrict__ A, const void* __restrict__ Al_,
              long sAbn, int lda,
              const void* __restrict__ B, const void* __restrict__ Bl_,
              long sBbn, int ldb,
              void* __restrict__ Cv, void* __restrict__ C2v, long sCbn, int ldc,
              const float* __restrict__ R, long sRbn,
              float* __restrict__ Op, int K)
{
    const int bx = blockIdx.x, by = blockIdx.y, bz = blockIdx.z;
    if (CAUSAL == 1 && bx > 2 * by + 1) return;

    constexpr int SS = 6144;
    extern __shared__ __align__(16) float sh[];

    const int tid = threadIdx.x;
    const int w = tid >> 5, l = tid & 31;
    const int warp_m = (w & 3) * 32, warp_n = (w >> 2) * 32;
    const int g = l >> 2, cc = l & 3;
    const int m0 = by * 128, n0 = bx * 64;

    const char* Abp  = (const char*)A + (long)bz * sAbn * 2;
    const char* Bbp  = (const char*)B + (long)bz * sBbn * 2;
    const char* Ablp = (MODE == 1) ? ((const char*)Al_ + (long)bz * sAbn * 2) : nullptr;
    const char* Bblp = (MODE == 1) ? ((const char*)Bl_ + (long)bz * sBbn * 2) : nullptr;

    int Keff = K;
    if (CAUSAL == 2) { int lim = m0 + 128; if (lim < Keff) Keff = lim; }
    const int nk = (MODE == 0) ? (Keff >> 6) : (Keff >> 5);

    const int am = tid >> 2, aj = tid & 3;
    const long oA0 = ((long)(m0 + am)      * lda + (long)aj * 8) * 2;
    const long oA1 = ((long)(m0 + am + 64) * lda + (long)aj * 8) * 2;
    const long oB  = ((long)(n0 + am)      * ldb + (long)aj * 8) * 2;
    const int swz  = ((aj ^ ((am >> 1) & 3)) & 3) << 2;
    const int slA0 = am * 16 + swz;
    const int slA1 = (am + 64) * 16 + swz;
    const int slB  = 2048 + am * 16 + swz;
    const uint32_t sbb = (uint32_t)__cvta_generic_to_shared(sh);

    auto issue = [&](int st, int kt) {
        uint32_t s0 = sbb + (uint32_t)(st * SS) * 4u;
        if (MODE == 0) {
            long kb = (long)kt * 128;
            CP16(s0 + slA0 * 4, Abp + oA0 + kb);
            CP16(s0 + slA1 * 4, Abp + oA1 + kb);
            CP16(s0 + slB  * 4, Bbp + oB  + kb);
            CP16(s0 + (slA0 + 3072) * 4, Abp + oA0 + kb + 64);
            CP16(s0 + (slA1 + 3072) * 4, Abp + oA1 + kb + 64);
            CP16(s0 + (slB  + 3072) * 4, Bbp + oB  + kb + 64);
        } else {
            long kb = (long)kt * 64;
            CP16(s0 + slA0 * 4, Abp + oA0 + kb);
            CP16(s0 + slA1 * 4, Abp + oA1 + kb);
            CP16(s0 + slB  * 4, Bbp + oB  + kb);
            CP16(s0 + (slA0 + 3072) * 4, Ablp + oA0 + kb);
            CP16(s0 + (slA1 + 3072) * 4, Ablp + oA1 + kb);
            CP16(s0 + (slB  + 3072) * 4, Bblp + oB  + kb);
        }
        asm volatile("cp.async.commit_group;\n" ::);
    };

    float acc[2][4][4] = {};

    issue(0, 0);
    if (nk > 1) issue(1, 1);
    else        asm volatile("cp.async.commit_group;\n" ::);

    for (int kt = 0; kt < nk; kt++) {
        asm volatile("cp.async.wait_group 1;\n" ::);
        __syncthreads();
        if (kt + 2 < nk) issue((kt + 2) % 3, kt + 2);
        else             asm volatile("cp.async.commit_group;\n" ::);

        const float* s0A = sh + (kt % 3) * SS;
        const float* s0B = s0A + 2048;
        const float* s1A = s0A + 3072;
        const float* s1B = s0A + 5120;

        float4 Ah[2][2], Bh[4], Al[2][2], Bl[4];
        #pragma unroll
        for (int mi = 0; mi < 2; mi++) {
            int mr = warp_m + mi * 16 + g;
            Ah[mi][0] = *(const float4*)&s0A[sw_addr(mr, cc)];
            Ah[mi][1] = *(const float4*)&s0A[sw_addr(mr + 8, cc)];
            Al[mi][0] = *(const float4*)&s1A[sw_addr(mr, cc)];
            Al[mi][1] = *(const float4*)&s1A[sw_addr(mr + 8, cc)];
        }
        #pragma unroll
        for (int nj = 0; nj < 4; nj++) {
            int nr = warp_n + nj * 8 + g;
            Bh[nj] = *(const float4*)&s0B[sw_addr(nr, cc)];
            Bl[nj] = *(const float4*)&s1B[sw_addr(nr, cc)];
        }

        #pragma unroll
        for (int mi = 0; mi < 2; mi++) {
            #pragma unroll
            for (int nj = 0; nj < 4; nj++) {
                float* d = acc[mi][nj];
                if (MODE == 0) {
                    MMA_F16(d, UF(Ah[mi][0].x), UF(Ah[mi][1].x), UF(Ah[mi][0].y), UF(Ah[mi][1].y),
                               UF(Bh[nj].x), UF(Bh[nj].y));
                    MMA_F16(d, UF(Ah[mi][0].z), UF(Ah[mi][1].z), UF(Ah[mi][0].w), UF(Ah[mi][1].w),
                               UF(Bh[nj].z), UF(Bh[nj].w));
                    MMA_F16(d, UF(Al[mi][0].x), UF(Al[mi][1].x), UF(Al[mi][0].y), UF(Al[mi][1].y),
                               UF(Bl[nj].x), UF(Bl[nj].y));
                    MMA_F16(d, UF(Al[mi][0].z), UF(Al[mi][1].z), UF(Al[mi][0].w), UF(Al[mi][1].w),
                               UF(Bl[nj].z), UF(Bl[nj].w));
                } else {
                    MMA_BF16(d, UF(Ah[mi][0].x), UF(Ah[mi][1].x), UF(Ah[mi][0].y), UF(Ah[mi][1].y),
                                UF(Bh[nj].x), UF(Bh[nj].y));
                    MMA_BF16(d, UF(Ah[mi][0].x), UF(Ah[mi][1].x), UF(Ah[mi][0].y), UF(Ah[mi][1].y),
                                UF(Bl[nj].x), UF(Bl[nj].y));
                    MMA_BF16(d, UF(Al[mi][0].x), UF(Al[mi][1].x), UF(Al[mi][0].y), UF(Al[mi][1].y),
                                UF(Bh[nj].x), UF(Bh[nj].y));
                    MMA_BF16(d, UF(Ah[mi][0].z), UF(Ah[mi][1].z), UF(Ah[mi][0].w), UF(Ah[mi][1].w),
                                UF(Bh[nj].z), UF(Bh[nj].w));
                    MMA_BF16(d, UF(Ah[mi][0].z), UF(Ah[mi][1].z), UF(Ah[mi][0].w), UF(Ah[mi][1].w),
                                UF(Bl[nj].z), UF(Bl[nj].w));
                    MMA_BF16(d, UF(Al[mi][0].z), UF(Al[mi][1].z), UF(Al[mi][0].w), UF(Al[mi][1].w),
                                UF(Bh[nj].z), UF(Bh[nj].w));
                }
            }
        }
    }

    // ---- epilogue ----
    if (EPI == 3) {
        const int b = bz >> 3, n = bz & 7;
        #pragma unroll
        for (int mi = 0; mi < 2; mi++) {
            #pragma unroll
            for (int nj = 0; nj < 4; nj++) {
                int row = m0 + warp_m + mi * 16 + g;
                int col = n0 + warp_n + nj * 8 + 2 * cc;
                Op[((long)(b * 64 + col)     * 8 + n) * 1024 + row]     = acc[mi][nj][0];
                Op[((long)(b * 64 + col + 1) * 8 + n) * 1024 + row]     = acc[mi][nj][1];
                Op[((long)(b * 64 + col)     * 8 + n) * 1024 + row + 8] = acc[mi][nj][2];
                Op[((long)(b * 64 + col + 1) * 8 + n) * 1024 + row + 8] = acc[mi][nj][3];
            }
        }
    } else if (EPI == 1 || EPI == 6) {
        __half* Cb = (__half*)Cv + (long)bz * sCbn;
        #pragma unroll
        for (int mi = 0; mi < 2; mi++) {
            #pragma unroll
            for (int nj = 0; nj < 4; nj++) {
                int row = m0 + warp_m + mi * 16 + g;
                int col = n0 + warp_n + nj * 8 + 2 * cc;
                int p0 = bperm(col);
                float v0 = acc[mi][nj][0], v1 = acc[mi][nj][1];
                float v2 = acc[mi][nj][2], v3 = acc[mi][nj][3];
                if (EPI == 1) {
                    v0 = fmaxf(v0, 0.f); v1 = fmaxf(v1, 0.f);
                    v2 = fmaxf(v2, 0.f); v3 = fmaxf(v3, 0.f);
                }
                *(__half2*)&Cb[(long)row * ldc + p0]       = __floats2half2_rn(v0, v1);
                *(__half2*)&Cb[(long)(row + 8) * ldc + p0] = __floats2half2_rn(v2, v3);
            }
        }
    } else if (EPI == 4 || EPI == 5) {
        __nv_bfloat16* Cb  = (__nv_bfloat16*)Cv  + (long)bz * sCbn;
        __nv_bfloat16* C2b = (__nv_bfloat16*)C2v + (long)bz * sCbn;
        const float* Rb = (EPI == 4) ? (R + (long)bz * sRbn) : nullptr;
        #pragma unroll
        for (int mi = 0; mi < 2; mi++) {
            #pragma unroll
            for (int nj = 0; nj < 4; nj++) {
                int row = m0 + warp_m + mi * 16 + g;
                int col = n0 + warp_n + nj * 8 + 2 * cc;
                int p0 = bperm(col);
                float v[4] = {acc[mi][nj][0], acc[mi][nj][1], acc[mi][nj][2], acc[mi][nj][3]};
                if (EPI == 4) {
                    float2 r0 = *(const float2*)(Rb + (long)row * ldc + col);
                    float2 r1 = *(const float2*)(Rb + (long)(row + 8) * ldc + col);
                    v[0] += r0.x; v[1] += r0.y; v[2] += r1.x; v[3] += r1.y;
                }
                __nv_bfloat16 h[4], lo[4];
                #pragma unroll
                for (int q = 0; q < 4; q++) bf16split(v[q], h[q], lo[q]);
                *(__nv_bfloat162*)&Cb [(long)row * ldc + p0]       = __nv_bfloat162(h[0],  h[1]);
                *(__nv_bfloat162*)&Cb [(long)(row + 8) * ldc + p0] = __nv_bfloat162(h[2],  h[3]);
                *(__nv_bfloat162*)&C2b[(long)row * ldc + p0]       = __nv_bfloat162(lo[0], lo[1]);
                *(__nv_bfloat162*)&C2b[(long)(row + 8) * ldc + p0] = __nv_bfloat162(lo[2], lo[3]);
            }
        }
    } else {
        float* Cb = (float*)Cv + (long)bz * sCbn;
        const float* Rb = (EPI == 2) ? (R + (long)bz * sRbn) : nullptr;
        #pragma unroll
        for (int mi = 0; mi < 2; mi++) {
            #pragma unroll
            for (int nj = 0; nj < 4; nj++) {
                int row = m0 + warp_m + mi * 16 + g;
                int col = n0 + warp_n + nj * 8 + 2 * cc;
                float v[4] = {acc[mi][nj][0], acc[mi][nj][1], acc[mi][nj][2], acc[mi][nj][3]};
                if (EPI == 2) {
                    float2 r0 = *(const float2*)(Rb + (long)row * ldc + col);
                    float2 r1 = *(const float2*)(Rb + (long)(row + 8) * ldc + col);
                    v[0] += r0.x; v[1] += r0.y; v[2] += r1.x; v[3] += r1.y;
                }
                *(float2*)(Cb + (long)row * ldc + col)       = make_float2(v[0], v[1]);
                *(float2*)(Cb + (long)(row + 8) * ldc + col) = make_float2(v[2], v[3]);
            }
        }
    }
}

// ---------------------------------------------------------------------------
// Weight prep: W_in -> bf16 split (bperm) + fp16 plain (bperm); W_out -> split;
// W1/W2 -> fp16 (bperm)
// ---------------------------------------------------------------------------
__global__ __launch_bounds__(256)
void wprep_k(const float* __restrict__ W_in, const float* __restrict__ W_out,
             const float* __restrict__ W1, const float* __restrict__ W2,
             __nv_bfloat16* __restrict__ wih, __nv_bfloat16* __restrict__ wil,
             __nv_bfloat16* __restrict__ woh, __nv_bfloat16* __restrict__ wol,
             __half* __restrict__ w1h, __half* __restrict__ w2h,
             __half* __restrict__ wifh)
{
    int i = blockIdx.x * 256 + threadIdx.x;
    const int nWi = DD * CD, nWo = CD * DD, nW1 = FD * DD;
    if (i < nWi) {
        int row = i / CD, k = i % CD;
        int o = row * CD + bperm(k);
        bf16split(W_in[i], wih[o], wil[o]);
        wifh[o] = __float2half_rn(W_in[i]);
    } else if (i < nWi + nWo) {
        int j = i - nWi;
        int row = j / DD, k = j % DD;
        int o = row * DD + bperm(k);
        bf16split(W_out[j], woh[o], wol[o]);
    } else if (i < nWi + nWo + nW1) {
        int j = i - nWi - nWo;
        int row = j / DD, k = j % DD;
        w1h[row * DD + bperm(k)] = __float2half_rn(W1[j]);
    } else {
        int j = i - nWi - nWo - nW1;
        if (j < DD * FD) {
            int row = j / FD, k = j % FD;
            w2h[row * FD + bperm(k)] = __float2half_rn(W2[j]);
        }
    }
}

// ---------------------------------------------------------------------------
// G = V^T V (66x66, padded to 128x96), V[c,j<64]=g_c*W_in[c,j], V[c,64]=-g_c,
// V[c,65]=b_c.  Stored split bf16 at gh[n*UK + bperm(k)].
// ---------------------------------------------------------------------------
__global__ __launch_bounds__(256)
void gprep_k(const float* __restrict__ W_in, const float* __restrict__ g1,
             const float* __restrict__ b1,
             __nv_bfloat16* __restrict__ gh, __nv_bfloat16* __restrict__ gl)
{
    int idx = blockIdx.x * 256 + threadIdx.x;
    if (idx >= 128 * UK) return;
    int n = idx / UK, k = idx % UK;
    float val = 0.f;
    if (n < 66 && k < 66) {
        for (int c = 0; c < DD; c++) {
            float gc = g1[c];
            float vn = (n < 64) ? gc * W_in[c * CD + n] : ((n == 64) ? -gc : b1[c]);
            float vk = (k < 64) ? gc * W_in[c * CD + k] : ((k == 64) ? -gc : b1[c]);
            val += vn * vk;
        }
    }
    __nv_bfloat16 h, lo;
    bf16split(val, h, lo);
    int o = n * UK + bperm(k);
    gh[o] = h; gl[o] = lo;
}

// ---------------------------------------------------------------------------
// transpose x: emits xt bf16 split (bperm c), xtf fp32 [s][c], xcs fp16 [c][bperm s]
// ---------------------------------------------------------------------------
__global__ __launch_bounds__(256)
void transpose_x_k(const float* __restrict__ x, __nv_bfloat16* __restrict__ xth,
                   __nv_bfloat16* __restrict__ xtl, float* __restrict__ xtf,
                   __half* __restrict__ xcs)
{
    __shared__ float tile[32][33];
    int tx = threadIdx.x & 31, ty = threadIdx.x >> 5;
    int bn = blockIdx.z, b = bn >> 3, n = bn & 7;
    int s0 = blockIdx.x * 32, c0 = blockIdx.y * 32;
    const float* src = x + ((long)b * 64 * 8 + n) * 1024;
    __half* xc = xcs + (long)bn * (CD * S);
    #pragma unroll
    for (int i = 0; i < 4; i++) {
        float v = src[(long)(c0 + ty + 8 * i) * 8192 + s0 + tx];
        tile[ty + 8 * i][tx] = v;
        // xcs[c][bperm(s)] — bperm preserves 32-blocks; s0+tx covers one block
        xc[(long)(c0 + ty + 8 * i) * S + bperm(s0 + tx)] = __float2half_rn(v);
    }
    __syncthreads();
    __nv_bfloat16* dh = xth + (long)bn * (S * CD);
    __nv_bfloat16* dl = xtl + (long)bn * (S * CD);
    float* df = xtf + (long)bn * (S * CD);
    int pc = bperm(c0 + tx);
    #pragma unroll
    for (int i = 0; i < 4; i++) {
        float v = tile[tx][ty + 8 * i];
        long row = (long)(s0 + ty + 8 * i);
        bf16split(v, dh[row * 64 + pc], dl[row * 64 + pc]);
        df[row * 64 + c0 + tx] = v;
    }
}

// ---------------------------------------------------------------------------
// LN1 stats only: murs[row] = {mu, rs}
// ---------------------------------------------------------------------------
__global__ __launch_bounds__(256)
void ln_stats_k(const float* __restrict__ in, float2* __restrict__ murs)
{
    int warp = (blockIdx.x * blockDim.x + threadIdx.x) >> 5;
    int lane = threadIdx.x & 31;
    const float* x = in + (long)warp * DD;

    float s = 0.f, ss = 0.f;
    #pragma unroll
    for (int i = 0; i < 8; i++) {
        float v = x[lane + 32 * i];
        s += v; ss += v * v;
    }
    #pragma unroll
    for (int o = 16; o; o >>= 1) {
        s  += __shfl_xor_sync(0xffffffffu, s,  o);
        ss += __shfl_xor_sync(0xffffffffu, ss, o);
    }
    float mu = s * (1.f / DD);
    float var = ss * (1.f / DD) - mu * mu;
    if (lane == 0) murs[warp] = make_float2(mu, rsqrtf(var + 1e-5f));
}

// ---------------------------------------------------------------------------
// Build U (S x 96, bf16 split, bperm k): U[i,j<64]=rs*x[i,j], U[i,64]=rs*mu,
// U[i,65]=1, else 0.  One warp per row.
// ---------------------------------------------------------------------------
__global__ __launch_bounds__(256)
void ubuild_k(const float* __restrict__ xtf, const float2* __restrict__ murs,
              __nv_bfloat16* __restrict__ uh, __nv_bfloat16* __restrict__ ul)
{
    int warp = (blockIdx.x * blockDim.x + threadIdx.x) >> 5;
    int lane = threadIdx.x & 31;
    float2 mr = murs[warp];
    const float* xr = xtf + (long)warp * CD;
    __nv_bfloat16* oh = uh + (long)warp * UK;
    __nv_bfloat16* ol = ul + (long)warp * UK;
    #pragma unroll
    for (int i = 0; i < 3; i++) {
        int j = lane + 32 * i;
        float v;
        if (j < 64)       v = mr.y * xr[j];
        else if (j == 64) v = mr.y * mr.x;
        else if (j == 65) v = 1.f;
        else              v = 0.f;
        bf16split(v, oh[bperm(j)], ol[bperm(j)]);
    }
}

// LN2 -> fp16 (bperm), feeds FFN1
__global__ __launch_bounds__(256)
void ln_half_k(const float* __restrict__ in, __half* __restrict__ out,
               const float* __restrict__ gam, const float* __restrict__ bet)
{
    int warp = (blockIdx.x * blockDim.x + threadIdx.x) >> 5;
    int lane = threadIdx.x & 31;
    const float* x = in + (long)warp * DD;

    float v[8], s = 0.f, ss = 0.f;
    #pragma unroll
    for (int i = 0; i < 8; i++) {
        v[i] = x[lane + 32 * i];
        s += v[i]; ss += v[i] * v[i];
    }
    #pragma unroll
    for (int o = 16; o; o >>= 1) {
        s  += __shfl_xor_sync(0xffffffffu, s,  o);
        ss += __shfl_xor_sync(0xffffffffu, ss, o);
    }
    float mu = s * (1.f / DD);
    float var = ss * (1.f / DD) - mu * mu;
    float rs = rsqrtf(var + 1e-5f);

    __half* o_ = out + (long)warp * DD;
    #pragma unroll
    for (int i = 0; i < 8; i++) {
        int c = lane + 32 * i;
        o_[bperm(c)] = __float2half_rn((v[i] - mu) * rs * gam[c] + bet[c]);
    }
}

// softmax: fp32 scores -> fp16 normalized p (bperm cols)
__global__ __launch_bounds__(256)
void softmax_k(const float* __restrict__ p, __half* __restrict__ ph)
{
    int warp = (blockIdx.x * blockDim.x + threadIdx.x) >> 5;
    int lane = threadIdx.x & 31;
    int q = warp & (S - 1);
    const float* row = p + (long)warp * S;
    __half* rowh = ph + (long)warp * S;

    float v[32], mx = -3.4e38f;
    #pragma unroll
    for (int i = 0; i < 32; i++) {
        int col = lane + 32 * i;
        v[i] = (col <= q) ? row[col] : -3.4e38f;
        mx = fmaxf(mx, v[i]);
    }
    #pragma unroll
    for (int o = 16; o; o >>= 1) mx = fmaxf(mx, __shfl_xor_sync(0xffffffffu, mx, o));

    float sum = 0.f;
    #pragma unroll
    for (int i = 0; i < 32; i++) {
        int col = lane + 32 * i;
        v[i] = (col <= q) ? expf(v[i] - mx) : 0.f;
        sum += v[i];
    }
    #pragma unroll
    for (int o = 16; o; o >>= 1) sum += __shfl_xor_sync(0xffffffffu, sum, o);
    float inv = 1.f / sum;

    int kend = ((q >> 7) + 1) << 7;
    #pragma unroll
    for (int i = 0; i < 32; i++) {
        int col = lane + 32 * i;
        if (col < kend) rowh[bperm(col)] = __float2half_rn(v[i] * inv);
    }
}

// ---------------------------------------------------------------------------
extern "C" void kernel_launch(void* const* d_in, const int* in_sizes, int n_in,
                              void* d_out, int out_size)
{
    (void)in_sizes; (void)n_in; (void)out_size;
    const float* buffer = (const float*)d_in[0];
    const float* W_in   = (const float*)d_in[1];
    const float* ln1_g  = (const float*)d_in[2];
    const float* ln1_b  = (const float*)d_in[3];
    const float* ln2_g  = (const float*)d_in[4];
    const float* ln2_b  = (const float*)d_in[5];
    const float* W1     = (const float*)d_in[6];
    const float* W2     = (const float*)d_in[7];
    const float* W_out  = (const float*)d_in[8];
    float* out = (float*)d_out;

    __nv_bfloat16 *xth, *xtl, *uh, *ul, *wh, *wl, *gh, *gl, *ybh, *ybl;
    __nv_bfloat16 *wih, *wil, *woh, *wol;
    __half *ph, *xcs, *pxh, *hnh, *hfh, *w1h, *w2h, *wifh;
    float *t, *xtf, *p, *att;
    float2* murs;
    cudaGetSymbolAddress((void**)&xth, g_xth);
    cudaGetSymbolAddress((void**)&xtl, g_xtl);
    cudaGetSymbolAddress((void**)&uh,  g_uh);
    cudaGetSymbolAddress((void**)&ul,  g_ul);
    cudaGetSymbolAddress((void**)&wh,  g_wh);
    cudaGetSymbolAddress((void**)&wl,  g_wl);
    cudaGetSymbolAddress((void**)&gh,  g_gh);
    cudaGetSymbolAddress((void**)&gl,  g_gl);
    cudaGetSymbolAddress((void**)&ybh, g_ybh);
    cudaGetSymbolAddress((void**)&ybl, g_ybl);
    cudaGetSymbolAddress((void**)&wih, g_wih);
    cudaGetSymbolAddress((void**)&wil, g_wil);
    cudaGetSymbolAddress((void**)&woh, g_woh);
    cudaGetSymbolAddress((void**)&wol, g_wol);
    cudaGetSymbolAddress((void**)&ph,  g_ph);
    cudaGetSymbolAddress((void**)&xcs, g_xcs);
    cudaGetSymbolAddress((void**)&pxh, g_pxh);
    cudaGetSymbolAddress((void**)&hnh, g_hnh);
    cudaGetSymbolAddress((void**)&hfh, g_hfh);
    cudaGetSymbolAddress((void**)&w1h, g_w1h);
    cudaGetSymbolAddress((void**)&w2h, g_w2h);
    cudaGetSymbolAddress((void**)&wifh, g_wifh);
    cudaGetSymbolAddress((void**)&t,   g_t);
    cudaGetSymbolAddress((void**)&xtf, g_xtf);
    cudaGetSymbolAddress((void**)&p,   g_p);
    cudaGetSymbolAddress((void**)&att, g_att);
    cudaGetSymbolAddress((void**)&murs, g_murs);

    const long sT = (long)S * DD;
    const long sP = (long)S * S;
    const long sH = (long)S * FD;
    const long sX = (long)S * CD;
    const long sU = (long)S * UK;
    const long sW = (long)S * 128;

    const int smem_b = 3 * 6144 * 4;
    cudaFuncSetAttribute(mma_gemm<1, 0, 0>, cudaFuncAttributeMaxDynamicSharedMemorySize, smem_b);
    cudaFuncSetAttribute(mma_gemm<1, 5, 0>, cudaFuncAttributeMaxDynamicSharedMemorySize, smem_b);
    cudaFuncSetAttribute(mma_gemm<1, 0, 1>, cudaFuncAttributeMaxDynamicSharedMemorySize, smem_b);
    cudaFuncSetAttribute(mma_gemm<0, 6, 2>, cudaFuncAttributeMaxDynamicSharedMemorySize, smem_b);
    cudaFuncSetAttribute(mma_gemm<0, 2, 0>, cudaFuncAttributeMaxDynamicSharedMemorySize, smem_b);
    cudaFuncSetAttribute(mma_gemm<0, 1, 0>, cudaFuncAttributeMaxDynamicSharedMemorySize, smem_b);
    cudaFuncSetAttribute(mma_gemm<0, 4, 0>, cudaFuncAttributeMaxDynamicSharedMemorySize, smem_b);
    cudaFuncSetAttribute(mma_gemm<1, 3, 0>, cudaFuncAttributeMaxDynamicSharedMemorySize, smem_b);

    // prep
    {
        const int ntot = DD * CD + CD * DD + FD * DD + DD * FD;
        wprep_k<<<(ntot + 255) / 256, 256>>>(W_in, W_out, W1, W2,
                                             wih, wil, woh, wol, w1h, w2h, wifh);
    }
    gprep_k<<<(128 * UK + 255) / 256, 256>>>(W_in, ln1_g, ln1_b, gh, gl);

    // 0) transpose x
    transpose_x_k<<<dim3(32, 2, BNT), 256>>>(buffer, xth, xtl, xtf, xcs);

    // 1) t = xt . W_in^T   (bf16 2-split)
    mma_gemm<1, 0, 0><<<dim3(4, 8, BNT), 256, smem_b>>>(
        xth, xtl, sX, CD,  wih, wil, 0, CD,
        t, nullptr, sT, DD,  nullptr, 0, nullptr, CD);

    // 2) LN1 stats, build U
    ln_stats_k<<<(BNT * S) / 8, 256>>>(t, murs);
    ubuild_k<<<(BNT * S) / 8, 256>>>(xtf, murs, uh, ul);

    // 3) W = U . G  (bf16 2-split, K=96) -> bf16 split, bperm cols
    mma_gemm<1, 5, 0><<<dim3(2, 8, BNT), 256, smem_b>>>(
        uh, ul, sU, UK,  gh, gl, 0, UK,
        wh, wl, sW, 128,  nullptr, 0, nullptr, UK);

    // 4) scores = W . U^T  (bf16 2-split, K=96, causal tile skip)
    mma_gemm<1, 0, 1><<<dim3(16, 8, BNT), 256, smem_b>>>(
        wh, wl, sW, 128,  uh, ul, sU, UK,
        p, nullptr, sP, S,  nullptr, 0, nullptr, UK);

    // 5) softmax -> fp16 p (bperm)
    softmax_k<<<(BNT * S) / 8, 256>>>(p, ph);

    // 6) px = p . x   (fp16, K limited) -> fp16 bperm cols
    mma_gemm<0, 6, 2><<<dim3(1, 8, BNT), 256, smem_b>>>(
        ph, nullptr, sP, S,  xcs, nullptr, (long)CD * S, S,
        pxh, nullptr, sX, CD,  nullptr, 0, nullptr, S);

    // 7) att = px . W_in^T + t   (fp16, K=64)
    mma_gemm<0, 2, 0><<<dim3(4, 8, BNT), 256, smem_b>>>(
        pxh, nullptr, sX, CD,  wifh, nullptr, 0, CD,
        att, nullptr, sT, DD,  t, sT, nullptr, CD);

    // 8) hn = LN2(att) -> fp16 (bperm)
    ln_half_k<<<(BNT * S) / 8, 256>>>(att, hnh, ln2_g, ln2_b);

    // 9) hf = relu(hn . W1^T)  (fp16)
    mma_gemm<0, 1, 0><<<dim3(8, 8, BNT), 256, smem_b>>>(
        hnh, nullptr, sT, DD,  w1h, nullptr, 0, DD,
        hfh, nullptr, sH, FD,  nullptr, 0, nullptr, DD);

    // 10) y = hf . W2^T + t -> bf16 hi/lo (bperm)
    mma_gemm<0, 4, 0><<<dim3(4, 8, BNT), 256, smem_b>>>(
        hfh, nullptr, sH, FD,  w2h, nullptr, 0, FD,
        ybh, ybl, sT, DD,  t, sT, nullptr, FD);

    // 11) out = y . W_out^T (bf16 2-split, scatter epilogue)
    mma_gemm<1, 3, 0><<<dim3(1, 8, BNT), 256, smem_b>>>(
        ybh, ybl, sT, DD,  woh, wol, 0, DD,
        nullptr, nullptr, 0, 0,  nullptr, 0, out, DD);
}

// round 11
// speedup vs baseline: 1.0676x; 1.0676x over previous
#include <cuda_runtime.h>
#include <cuda_bf16.h>
#include <cuda_fp16.h>
#include <cstdint>

#define S    1024
#define CD   64
#define DD   256
#define FD   512
#define BNT  32
#define UK   96      // padded low-rank K (66 -> 96)

// bf16 split operands (bperm layout)
__device__ __align__(256) __nv_bfloat16 g_xth[BNT * S * CD];
__device__ __align__(256) __nv_bfloat16 g_xtl[BNT * S * CD];
__device__ __align__(256) __nv_bfloat16 g_uh [BNT * S * UK];
__device__ __align__(256) __nv_bfloat16 g_ul [BNT * S * UK];
__device__ __align__(256) __nv_bfloat16 g_wwh[BNT * S * 128];
__device__ __align__(256) __nv_bfloat16 g_wwl[BNT * S * 128];
__device__ __align__(256) __nv_bfloat16 g_gh [128 * UK];
__device__ __align__(256) __nv_bfloat16 g_gl [128 * UK];
__device__ __align__(256) __nv_bfloat16 g_ybh[BNT * S * DD];
__device__ __align__(256) __nv_bfloat16 g_ybl[BNT * S * DD];
__device__ __align__(256) __nv_bfloat16 g_wih[DD * CD];
__device__ __align__(256) __nv_bfloat16 g_wil[DD * CD];
__device__ __align__(256) __nv_bfloat16 g_woh[CD * DD];
__device__ __align__(256) __nv_bfloat16 g_wol[CD * DD];
// fp16 operands (bperm layout)
__device__ __align__(256) __half g_ph [(long)BNT * S * S];
__device__ __align__(256) __half g_tTh[BNT * S * DD];
__device__ __align__(256) __half g_hnh[BNT * S * DD];
__device__ __align__(256) __half g_hfh[BNT * S * FD];
__device__ __align__(256) __half g_w1h[FD * DD];
__device__ __align__(256) __half g_w2h[DD * FD];
// fp32
__device__ __align__(256) float g_t  [BNT * S * DD];
__device__ __align__(256) float g_xtf[BNT * S * CD];
__device__ __align__(256) float g_p  [(long)BNT * S * S];
__device__ __align__(256) float g_att[BNT * S * DD];

// ---------------------------------------------------------------------------
__device__ __forceinline__ int bperm(int k) {   // 16-bit k-perm within 32
    return (k & ~31) | (((k >> 1) & 3) << 3) | (((k >> 3) & 3) << 1) | (k & 1);
}

#define MMA_BF16(d, a0, a1, a2, a3, b0, b1)                                   \
    asm volatile("mma.sync.aligned.m16n8k16.row.col.f32.bf16.bf16.f32 "       \
                 "{%0,%1,%2,%3}, {%4,%5,%6,%7}, {%8,%9}, {%0,%1,%2,%3};\n"    \
                 : "+f"(d[0]), "+f"(d[1]), "+f"(d[2]), "+f"(d[3])             \
                 : "r"(a0), "r"(a1), "r"(a2), "r"(a3), "r"(b0), "r"(b1))

#define MMA_F16(d, a0, a1, a2, a3, b0, b1)                                    \
    asm volatile("mma.sync.aligned.m16n8k16.row.col.f32.f16.f16.f32 "         \
                 "{%0,%1,%2,%3}, {%4,%5,%6,%7}, {%8,%9}, {%0,%1,%2,%3};\n"    \
                 : "+f"(d[0]), "+f"(d[1]), "+f"(d[2]), "+f"(d[3])             \
                 : "r"(a0), "r"(a1), "r"(a2), "r"(a3), "r"(b0), "r"(b1))

#define UF(x) __float_as_uint(x)

#define CP16(dst, src)                                                        \
    asm volatile("cp.async.cg.shared.global [%0], [%1], 16;\n"                \
                 :: "r"(dst), "l"(src))

__device__ __forceinline__ int sw_addr(int m, int q) {
    return m * 16 + (((q ^ ((m >> 1) & 3)) & 3) << 2);
}

__device__ __forceinline__ void bf16split(float v, __nv_bfloat16& h, __nv_bfloat16& l) {
    h = __float2bfloat16_rn(v);
    l = __float2bfloat16_rn(v - __bfloat162float(h));
}

// ---------------------------------------------------------------------------
// cp.async 3-stage pipelined MMA GEMM (round-8 core).
// MODE 0: fp16 single-pass, BK=64.  MODE 1: bf16 2-term split, BK=32.
// EPI 0: fp32 store  1: relu->fp16 bperm  2: +R->fp32  3: scatter to output
//     4: +R->bf16 split bperm  5: bf16 split bperm (no R)
// CAUSAL 1: tile skip (scores); 2: K limited to m0+128 (P@V)
// ---------------------------------------------------------------------------
template<int MODE, int EPI, int CAUSAL>
__global__ __launch_bounds__(256, 2)
void mma_gemm(const void* __restrict__ A, const void* __restrict__ Al_,
              long sAbn, int lda,
              const void* __restrict__ B, const void* __restrict__ Bl_,
              long sBbn, int ldb,
              void* __restrict__ Cv, void* __restrict__ C2v, long sCbn, int ldc,
              const float* __restrict__ R, long sRbn,
              float* __restrict__ Op, int K)
{
    const int bx = blockIdx.x, by = blockIdx.y, bz = blockIdx.z;
    if (CAUSAL == 1 && bx > 2 * by + 1) return;

    constexpr int SS = 6144;
    extern __shared__ __align__(16) float sh[];

    const int tid = threadIdx.x;
    const int w = tid >> 5, l = tid & 31;
    const int warp_m = (w & 3) * 32, warp_n = (w >> 2) * 32;
    const int g = l >> 2, cc = l & 3;
    const int m0 = by * 128, n0 = bx * 64;

    const char* Abp  = (const char*)A + (long)bz * sAbn * 2;
    const char* Bbp  = (const char*)B + (long)bz * sBbn * 2;
    const char* Ablp = (MODE == 1) ? ((const char*)Al_ + (long)bz * sAbn * 2) : nullptr;
    const char* Bblp = (MODE == 1) ? ((const char*)Bl_ + (long)bz * sBbn * 2) : nullptr;

    int Keff = K;
    if (CAUSAL == 2) { int lim = m0 + 128; if (lim < Keff) Keff = lim; }
    const int nk = (MODE == 0) ? (Keff >> 6) : (Keff >> 5);

    const int am = tid >> 2, aj = tid & 3;
    const long oA0 = ((long)(m0 + am)      * lda + (long)aj * 8) * 2;
    const long oA1 = ((long)(m0 + am + 64) * lda + (long)aj * 8) * 2;
    const long oB  = ((long)(n0 + am)      * ldb + (long)aj * 8) * 2;
    const int swz  = ((aj ^ ((am >> 1) & 3)) & 3) << 2;
    const int slA0 = am * 16 + swz;
    const int slA1 = (am + 64) * 16 + swz;
    const int slB  = 2048 + am * 16 + swz;
    const uint32_t sbb = (uint32_t)__cvta_generic_to_shared(sh);

    auto issue = [&](int st, int kt) {
        uint32_t s0 = sbb + (uint32_t)(st * SS) * 4u;
        if (MODE == 0) {
            long kb = (long)kt * 128;
            CP16(s0 + slA0 * 4, Abp + oA0 + kb);
            CP16(s0 + slA1 * 4, Abp + oA1 + kb);
            CP16(s0 + slB  * 4, Bbp + oB  + kb);
            CP16(s0 + (slA0 + 3072) * 4, Abp + oA0 + kb + 64);
            CP16(s0 + (slA1 + 3072) * 4, Abp + oA1 + kb + 64);
            CP16(s0 + (slB  + 3072) * 4, Bbp + oB  + kb + 64);
        } else {
            long kb = (long)kt * 64;
            CP16(s0 + slA0 * 4, Abp + oA0 + kb);
            CP16(s0 + slA1 * 4, Abp + oA1 + kb);
            CP16(s0 + slB  * 4, Bbp + oB  + kb);
            CP16(s0 + (slA0 + 3072) * 4, Ablp + oA0 + kb);
            CP16(s0 + (slA1 + 3072) * 4, Ablp + oA1 + kb);
            CP16(s0 + (slB  + 3072) * 4, Bblp + oB  + kb);
        }
        asm volatile("cp.async.commit_group;\n" ::);
    };

    float acc[2][4][4] = {};

    issue(0, 0);
    if (nk > 1) issue(1, 1);
    else        asm volatile("cp.async.commit_group;\n" ::);

    for (int kt = 0; kt < nk; kt++) {
        asm volatile("cp.async.wait_group 1;\n" ::);
        __syncthreads();
        if (kt + 2 < nk) issue((kt + 2) % 3, kt + 2);
        else             asm volatile("cp.async.commit_group;\n" ::);

        const float* s0A = sh + (kt % 3) * SS;
        const float* s0B = s0A + 2048;
        const float* s1A = s0A + 3072;
        const float* s1B = s0A + 5120;

        float4 Ah[2][2], Bh[4], Al[2][2], Bl[4];
        #pragma unroll
        for (int mi = 0; mi < 2; mi++) {
            int mr = warp_m + mi * 16 + g;
            Ah[mi][0] = *(const float4*)&s0A[sw_addr(mr, cc)];
            Ah[mi][1] = *(const float4*)&s0A[sw_addr(mr + 8, cc)];
            Al[mi][0] = *(const float4*)&s1A[sw_addr(mr, cc)];
            Al[mi][1] = *(const float4*)&s1A[sw_addr(mr + 8, cc)];
        }
        #pragma unroll
        for (int nj = 0; nj < 4; nj++) {
            int nr = warp_n + nj * 8 + g;
            Bh[nj] = *(const float4*)&s0B[sw_addr(nr, cc)];
            Bl[nj] = *(const float4*)&s1B[sw_addr(nr, cc)];
        }

        #pragma unroll
        for (int mi = 0; mi < 2; mi++) {
            #pragma unroll
            for (int nj = 0; nj < 4; nj++) {
                float* d = acc[mi][nj];
                if (MODE == 0) {
                    MMA_F16(d, UF(Ah[mi][0].x), UF(Ah[mi][1].x), UF(Ah[mi][0].y), UF(Ah[mi][1].y),
                               UF(Bh[nj].x), UF(Bh[nj].y));
                    MMA_F16(d, UF(Ah[mi][0].z), UF(Ah[mi][1].z), UF(Ah[mi][0].w), UF(Ah[mi][1].w),
                               UF(Bh[nj].z), UF(Bh[nj].w));
                    MMA_F16(d, UF(Al[mi][0].x), UF(Al[mi][1].x), UF(Al[mi][0].y), UF(Al[mi][1].y),
                               UF(Bl[nj].x), UF(Bl[nj].y));
                    MMA_F16(d, UF(Al[mi][0].z), UF(Al[mi][1].z), UF(Al[mi][0].w), UF(Al[mi][1].w),
                               UF(Bl[nj].z), UF(Bl[nj].w));
                } else {
                    MMA_BF16(d, UF(Ah[mi][0].x), UF(Ah[mi][1].x), UF(Ah[mi][0].y), UF(Ah[mi][1].y),
                                UF(Bh[nj].x), UF(Bh[nj].y));
                    MMA_BF16(d, UF(Ah[mi][0].x), UF(Ah[mi][1].x), UF(Ah[mi][0].y), UF(Ah[mi][1].y),
                                UF(Bl[nj].x), UF(Bl[nj].y));
                    MMA_BF16(d, UF(Al[mi][0].x), UF(Al[mi][1].x), UF(Al[mi][0].y), UF(Al[mi][1].y),
                                UF(Bh[nj].x), UF(Bh[nj].y));
                    MMA_BF16(d, UF(Ah[mi][0].z), UF(Ah[mi][1].z), UF(Ah[mi][0].w), UF(Ah[mi][1].w),
                                UF(Bh[nj].z), UF(Bh[nj].w));
                    MMA_BF16(d, UF(Ah[mi][0].z), UF(Ah[mi][1].z), UF(Ah[mi][0].w), UF(Ah[mi][1].w),
                                UF(Bl[nj].z), UF(Bl[nj].w));
                    MMA_BF16(d, UF(Al[mi][0].z), UF(Al[mi][1].z), UF(Al[mi][0].w), UF(Al[mi][1].w),
                                UF(Bh[nj].z), UF(Bh[nj].w));
                }
            }
        }
    }

    // ---- epilogue ----
    if (EPI == 3) {
        const int b = bz >> 3, n = bz & 7;
        #pragma unroll
        for (int mi = 0; mi < 2; mi++) {
            #pragma unroll
            for (int nj = 0; nj < 4; nj++) {
                int row = m0 + warp_m + mi * 16 + g;
                int col = n0 + warp_n + nj * 8 + 2 * cc;
                Op[((long)(b * 64 + col)     * 8 + n) * 1024 + row]     = acc[mi][nj][0];
                Op[((long)(b * 64 + col + 1) * 8 + n) * 1024 + row]     = acc[mi][nj][1];
                Op[((long)(b * 64 + col)     * 8 + n) * 1024 + row + 8] = acc[mi][nj][2];
                Op[((long)(b * 64 + col + 1) * 8 + n) * 1024 + row + 8] = acc[mi][nj][3];
            }
        }
    } else if (EPI == 1) {
        __half* Cb = (__half*)Cv + (long)bz * sCbn;
        #pragma unroll
        for (int mi = 0; mi < 2; mi++) {
            #pragma unroll
            for (int nj = 0; nj < 4; nj++) {
                int row = m0 + warp_m + mi * 16 + g;
                int col = n0 + warp_n + nj * 8 + 2 * cc;
                int p0 = bperm(col);
                *(__half2*)&Cb[(long)row * ldc + p0] =
                    __floats2half2_rn(fmaxf(acc[mi][nj][0], 0.f), fmaxf(acc[mi][nj][1], 0.f));
                *(__half2*)&Cb[(long)(row + 8) * ldc + p0] =
                    __floats2half2_rn(fmaxf(acc[mi][nj][2], 0.f), fmaxf(acc[mi][nj][3], 0.f));
            }
        }
    } else if (EPI == 4 || EPI == 5) {
        __nv_bfloat16* Cb  = (__nv_bfloat16*)Cv  + (long)bz * sCbn;
        __nv_bfloat16* C2b = (__nv_bfloat16*)C2v + (long)bz * sCbn;
        const float* Rb = (EPI == 4) ? (R + (long)bz * sRbn) : nullptr;
        #pragma unroll
        for (int mi = 0; mi < 2; mi++) {
            #pragma unroll
            for (int nj = 0; nj < 4; nj++) {
                int row = m0 + warp_m + mi * 16 + g;
                int col = n0 + warp_n + nj * 8 + 2 * cc;
                int p0 = bperm(col);
                float v[4] = {acc[mi][nj][0], acc[mi][nj][1], acc[mi][nj][2], acc[mi][nj][3]};
                if (EPI == 4) {
                    float2 r0 = *(const float2*)(Rb + (long)row * ldc + col);
                    float2 r1 = *(const float2*)(Rb + (long)(row + 8) * ldc + col);
                    v[0] += r0.x; v[1] += r0.y; v[2] += r1.x; v[3] += r1.y;
                }
                __nv_bfloat16 h[4], lo[4];
                #pragma unroll
                for (int q = 0; q < 4; q++) bf16split(v[q], h[q], lo[q]);
                *(__nv_bfloat162*)&Cb [(long)row * ldc + p0]       = __nv_bfloat162(h[0],  h[1]);
                *(__nv_bfloat162*)&Cb [(long)(row + 8) * ldc + p0] = __nv_bfloat162(h[2],  h[3]);
                *(__nv_bfloat162*)&C2b[(long)row * ldc + p0]       = __nv_bfloat162(lo[0], lo[1]);
                *(__nv_bfloat162*)&C2b[(long)(row + 8) * ldc + p0] = __nv_bfloat162(lo[2], lo[3]);
            }
        }
    } else {
        float* Cb = (float*)Cv + (long)bz * sCbn;
        const float* Rb = (EPI == 2) ? (R + (long)bz * sRbn) : nullptr;
        #pragma unroll
        for (int mi = 0; mi < 2; mi++) {
            #pragma unroll
            for (int nj = 0; nj < 4; nj++) {
                int row = m0 + warp_m + mi * 16 + g;
                int col = n0 + warp_n + nj * 8 + 2 * cc;
                float v[4] = {acc[mi][nj][0], acc[mi][nj][1], acc[mi][nj][2], acc[mi][nj][3]};
                if (EPI == 2) {
                    float2 r0 = *(const float2*)(Rb + (long)row * ldc + col);
                    float2 r1 = *(const float2*)(Rb + (long)(row + 8) * ldc + col);
                    v[0] += r0.x; v[1] += r0.y; v[2] += r1.x; v[3] += r1.y;
                }
                *(float2*)(Cb + (long)row * ldc + col)       = make_float2(v[0], v[1]);
                *(float2*)(Cb + (long)(row + 8) * ldc + col) = make_float2(v[2], v[3]);
            }
        }
    }
}

// ---------------------------------------------------------------------------
// Weight prep
// ---------------------------------------------------------------------------
__global__ __launch_bounds__(256)
void wprep_k(const float* __restrict__ W_in, const float* __restrict__ W_out,
             const float* __restrict__ W1, const float* __restrict__ W2,
             __nv_bfloat16* __restrict__ wih, __nv_bfloat16* __restrict__ wil,
             __nv_bfloat16* __restrict__ woh, __nv_bfloat16* __restrict__ wol,
             __half* __restrict__ w1h, __half* __restrict__ w2h)
{
    int i = blockIdx.x * 256 + threadIdx.x;
    const int nWi = DD * CD, nWo = CD * DD, nW1 = FD * DD;
    if (i < nWi) {
        int row = i / CD, k = i % CD;
        int o = row * CD + bperm(k);
        bf16split(W_in[i], wih[o], wil[o]);
    } else if (i < nWi + nWo) {
        int j = i - nWi;
        int row = j / DD, k = j % DD;
        int o = row * DD + bperm(k);
        bf16split(W_out[j], woh[o], wol[o]);
    } else if (i < nWi + nWo + nW1) {
        int j = i - nWi - nWo;
        int row = j / DD, k = j % DD;
        w1h[row * DD + bperm(k)] = __float2half_rn(W1[j]);
    } else {
        int j = i - nWi - nWo - nW1;
        if (j < DD * FD) {
            int row = j / FD, k = j % FD;
            w2h[row * FD + bperm(k)] = __float2half_rn(W2[j]);
        }
    }
}

// ---------------------------------------------------------------------------
// G = V^T V (coalesced, V cached in smem). V[c,j<64]=g_c*W_in[c,j],
// V[c,64]=-g_c, V[c,65]=b_c, else 0. 48 blocks x 256 outputs each.
// ---------------------------------------------------------------------------
__global__ __launch_bounds__(256)
void gprep_k(const float* __restrict__ W_in, const float* __restrict__ g1,
             const float* __restrict__ b1,
             __nv_bfloat16* __restrict__ gh, __nv_bfloat16* __restrict__ gl)
{
    extern __shared__ float sV[];   // [256][96]
    const int tid = threadIdx.x;
    for (int idx = tid; idx < DD * UK; idx += 256) {
        int c = idx / UK, j = idx % UK;
        float gc = g1[c];
        float v = (j < 64) ? gc * W_in[c * CD + j] : ((j == 64) ? -gc : ((j == 65) ? b1[c] : 0.f));
        sV[idx] = v;
    }
    __syncthreads();
    int oidx = blockIdx.x * 256 + tid;
    if (oidx >= 128 * UK) return;
    int n = oidx / UK, k = oidx % UK;
    float val = 0.f;
    if (n < 66 && k < 66) {
        #pragma unroll 4
        for (int c = 0; c < DD; c++)
            val += sV[c * UK + n] * sV[c * UK + k];
    }
    __nv_bfloat16 h, lo;
    bf16split(val, h, lo);
    int o = n * UK + bperm(k);
    gh[o] = h; gl[o] = lo;
}

// ---------------------------------------------------------------------------
// transpose x: xt bf16 split (bperm c) + xtf fp32 [s][c]
// ---------------------------------------------------------------------------
__global__ __launch_bounds__(256)
void transpose_x_k(const float* __restrict__ x, __nv_bfloat16* __restrict__ xth,
                   __nv_bfloat16* __restrict__ xtl, float* __restrict__ xtf)
{
    __shared__ float tile[32][33];
    int tx = threadIdx.x & 31, ty = threadIdx.x >> 5;
    int bn = blockIdx.z, b = bn >> 3, n = bn & 7;
    int s0 = blockIdx.x * 32, c0 = blockIdx.y * 32;
    const float* src = x + ((long)b * 64 * 8 + n) * 1024;
    #pragma unroll
    for (int i = 0; i < 4; i++)
        tile[ty + 8 * i][tx] = src[(long)(c0 + ty + 8 * i) * 8192 + s0 + tx];
    __syncthreads();
    __nv_bfloat16* dh = xth + (long)bn * (S * CD);
    __nv_bfloat16* dl = xtl + (long)bn * (S * CD);
    float* df = xtf + (long)bn * (S * CD);
    int pc = bperm(c0 + tx);
    #pragma unroll
    for (int i = 0; i < 4; i++) {
        float v = tile[tx][ty + 8 * i];
        long row = (long)(s0 + ty + 8 * i);
        bf16split(v, dh[row * 64 + pc], dl[row * 64 + pc]);
        df[row * 64 + c0 + tx] = v;
    }
}

// ---------------------------------------------------------------------------
// LN1 stats from t + build U (S x 96, bf16 split, bperm). One warp per row.
// U[i,j<64]=rs*x[i,j], U[i,64]=rs*mu, U[i,65]=1, else 0.
// ---------------------------------------------------------------------------
__global__ __launch_bounds__(256)
void stats_ubuild_k(const float* __restrict__ t, const float* __restrict__ xtf,
                    __nv_bfloat16* __restrict__ uh, __nv_bfloat16* __restrict__ ul)
{
    int warp = (blockIdx.x * blockDim.x + threadIdx.x) >> 5;
    int lane = threadIdx.x & 31;
    const float* x = t + (long)warp * DD;

    float s = 0.f, ss = 0.f;
    #pragma unroll
    for (int i = 0; i < 8; i++) {
        float v = x[lane + 32 * i];
        s += v; ss += v * v;
    }
    #pragma unroll
    for (int o = 16; o; o >>= 1) {
        s  += __shfl_xor_sync(0xffffffffu, s,  o);
        ss += __shfl_xor_sync(0xffffffffu, ss, o);
    }
    float mu = s * (1.f / DD);
    float var = ss * (1.f / DD) - mu * mu;
    float rs = rsqrtf(var + 1e-5f);

    const float* xr = xtf + (long)warp * CD;
    __nv_bfloat16* oh = uh + (long)warp * UK;
    __nv_bfloat16* ol = ul + (long)warp * UK;
    #pragma unroll
    for (int i = 0; i < 3; i++) {
        int j = lane + 32 * i;
        float v;
        if (j < 64)       v = rs * xr[j];
        else if (j == 64) v = rs * mu;
        else if (j == 65) v = 1.f;
        else              v = 0.f;
        __nv_bfloat16 h, lo;
        bf16split(v, h, lo);
        oh[bperm(j)] = h; ol[bperm(j)] = lo;
    }
}

// t -> tT fp16 [d][s], bperm on s
__global__ __launch_bounds__(256)
void transpose_t_k(const float* __restrict__ t, __half* __restrict__ tT)
{
    __shared__ float tile[32][33];
    int tx = threadIdx.x & 31, ty = threadIdx.x >> 5;
    int bn = blockIdx.z;
    int s0 = blockIdx.x * 32, d0 = blockIdx.y * 32;
    const float* src = t + (long)bn * (S * DD);
    #pragma unroll
    for (int i = 0; i < 4; i++)
        tile[ty + 8 * i][tx] = src[(long)(s0 + ty + 8 * i) * 256 + d0 + tx];
    __syncthreads();
    __half* dst = tT + (long)bn * (S * DD);
    int ps = bperm(s0 + tx);
    #pragma unroll
    for (int i = 0; i < 4; i++)
        dst[(long)(d0 + ty + 8 * i) * 1024 + ps] = __float2half_rn(tile[tx][ty + 8 * i]);
}

// LN2 -> fp16 (bperm)
__global__ __launch_bounds__(256)
void ln_half_k(const float* __restrict__ in, __half* __restrict__ out,
               const float* __restrict__ gam, const float* __restrict__ bet)
{
    int warp = (blockIdx.x * blockDim.x + threadIdx.x) >> 5;
    int lane = threadIdx.x & 31;
    const float* x = in + (long)warp * DD;

    float v[8], s = 0.f, ss = 0.f;
    #pragma unroll
    for (int i = 0; i < 8; i++) {
        v[i] = x[lane + 32 * i];
        s += v[i]; ss += v[i] * v[i];
    }
    #pragma unroll
    for (int o = 16; o; o >>= 1) {
        s  += __shfl_xor_sync(0xffffffffu, s,  o);
        ss += __shfl_xor_sync(0xffffffffu, ss, o);
    }
    float mu = s * (1.f / DD);
    float var = ss * (1.f / DD) - mu * mu;
    float rs = rsqrtf(var + 1e-5f);

    __half* o_ = out + (long)warp * DD;
    #pragma unroll
    for (int i = 0; i < 8; i++) {
        int c = lane + 32 * i;
        o_[bperm(c)] = __float2half_rn((v[i] - mu) * rs * gam[c] + bet[c]);
    }
}

// softmax: fp32 scores -> fp16 normalized p (bperm cols)
__global__ __launch_bounds__(256)
void softmax_k(const float* __restrict__ p, __half* __restrict__ ph)
{
    int warp = (blockIdx.x * blockDim.x + threadIdx.x) >> 5;
    int lane = threadIdx.x & 31;
    int q = warp & (S - 1);
    const float* row = p + (long)warp * S;
    __half* rowh = ph + (long)warp * S;

    float v[32], mx = -3.4e38f;
    #pragma unroll
    for (int i = 0; i < 32; i++) {
        int col = lane + 32 * i;
        v[i] = (col <= q) ? row[col] : -3.4e38f;
        mx = fmaxf(mx, v[i]);
    }
    #pragma unroll
    for (int o = 16; o; o >>= 1) mx = fmaxf(mx, __shfl_xor_sync(0xffffffffu, mx, o));

    float sum = 0.f;
    #pragma unroll
    for (int i = 0; i < 32; i++) {
        int col = lane + 32 * i;
        v[i] = (col <= q) ? expf(v[i] - mx) : 0.f;
        sum += v[i];
    }
    #pragma unroll
    for (int o = 16; o; o >>= 1) sum += __shfl_xor_sync(0xffffffffu, sum, o);
    float inv = 1.f / sum;

    int kend = ((q >> 7) + 1) << 7;
    #pragma unroll
    for (int i = 0; i < 32; i++) {
        int col = lane + 32 * i;
        if (col < kend) rowh[bperm(col)] = __float2half_rn(v[i] * inv);
    }
}

// ---------------------------------------------------------------------------
extern "C" void kernel_launch(void* const* d_in, const int* in_sizes, int n_in,
                              void* d_out, int out_size)
{
    (void)in_sizes; (void)n_in; (void)out_size;
    const float* buffer = (const float*)d_in[0];
    const float* W_in   = (const float*)d_in[1];
    const float* ln1_g  = (const float*)d_in[2];
    const float* ln1_b  = (const float*)d_in[3];
    const float* ln2_g  = (const float*)d_in[4];
    const float* ln2_b  = (const float*)d_in[5];
    const float* W1     = (const float*)d_in[6];
    const float* W2     = (const float*)d_in[7];
    const float* W_out  = (const float*)d_in[8];
    float* out = (float*)d_out;

    __nv_bfloat16 *xth, *xtl, *uh, *ul, *wwh, *wwl, *gh, *gl, *ybh, *ybl;
    __nv_bfloat16 *wih, *wil, *woh, *wol;
    __half *ph, *tTh, *hnh, *hfh, *w1h, *w2h;
    float *t, *xtf, *p, *att;
    cudaGetSymbolAddress((void**)&xth, g_xth);
    cudaGetSymbolAddress((void**)&xtl, g_xtl);
    cudaGetSymbolAddress((void**)&uh,  g_uh);
    cudaGetSymbolAddress((void**)&ul,  g_ul);
    cudaGetSymbolAddress((void**)&wwh, g_wwh);
    cudaGetSymbolAddress((void**)&wwl, g_wwl);
    cudaGetSymbolAddress((void**)&gh,  g_gh);
    cudaGetSymbolAddress((void**)&gl,  g_gl);
    cudaGetSymbolAddress((void**)&ybh, g_ybh);
    cudaGetSymbolAddress((void**)&ybl, g_ybl);
    cudaGetSymbolAddress((void**)&wih, g_wih);
    cudaGetSymbolAddress((void**)&wil, g_wil);
    cudaGetSymbolAddress((void**)&woh, g_woh);
    cudaGetSymbolAddress((void**)&wol, g_wol);
    cudaGetSymbolAddress((void**)&ph,  g_ph);
    cudaGetSymbolAddress((void**)&tTh, g_tTh);
    cudaGetSymbolAddress((void**)&hnh, g_hnh);
    cudaGetSymbolAddress((void**)&hfh, g_hfh);
    cudaGetSymbolAddress((void**)&w1h, g_w1h);
    cudaGetSymbolAddress((void**)&w2h, g_w2h);
    cudaGetSymbolAddress((void**)&t,   g_t);
    cudaGetSymbolAddress((void**)&xtf, g_xtf);
    cudaGetSymbolAddress((void**)&p,   g_p);
    cudaGetSymbolAddress((void**)&att, g_att);

    const long sT = (long)S * DD;
    const long sP = (long)S * S;
    const long sH = (long)S * FD;
    const long sX = (long)S * CD;
    const long sU = (long)S * UK;
    const long sWL = (long)S * 128;

    const int smem_b = 3 * 6144 * 4;
    const int smem_g = DD * UK * 4;   // 98304
    cudaFuncSetAttribute(mma_gemm<1, 0, 0>, cudaFuncAttributeMaxDynamicSharedMemorySize, smem_b);
    cudaFuncSetAttribute(mma_gemm<1, 5, 0>, cudaFuncAttributeMaxDynamicSharedMemorySize, smem_b);
    cudaFuncSetAttribute(mma_gemm<1, 0, 1>, cudaFuncAttributeMaxDynamicSharedMemorySize, smem_b);
    cudaFuncSetAttribute(mma_gemm<0, 2, 2>, cudaFuncAttributeMaxDynamicSharedMemorySize, smem_b);
    cudaFuncSetAttribute(mma_gemm<0, 1, 0>, cudaFuncAttributeMaxDynamicSharedMemorySize, smem_b);
    cudaFuncSetAttribute(mma_gemm<0, 4, 0>, cudaFuncAttributeMaxDynamicSharedMemorySize, smem_b);
    cudaFuncSetAttribute(mma_gemm<1, 3, 0>, cudaFuncAttributeMaxDynamicSharedMemorySize, smem_b);
    cudaFuncSetAttribute(gprep_k, cudaFuncAttributeMaxDynamicSharedMemorySize, smem_g);

    // prep
    {
        const int ntot = DD * CD + CD * DD + FD * DD + DD * FD;
        wprep_k<<<(ntot + 255) / 256, 256>>>(W_in, W_out, W1, W2,
                                             wih, wil, woh, wol, w1h, w2h);
    }
    gprep_k<<<(128 * UK + 255) / 256, 256, smem_g>>>(W_in, ln1_g, ln1_b, gh, gl);

    // 0) transpose x -> xt bf16 split + xtf fp32
    transpose_x_k<<<dim3(32, 2, BNT), 256>>>(buffer, xth, xtl, xtf);

    // 1) t = xt . W_in^T   (bf16 2-split)
    mma_gemm<1, 0, 0><<<dim3(4, 8, BNT), 256, smem_b>>>(
        xth, xtl, sX, CD,  wih, wil, 0, CD,
        t, nullptr, sT, DD,  nullptr, 0, nullptr, CD);

    // 2) LN1 stats + build U
    stats_ubuild_k<<<(BNT * S) / 8, 256>>>(t, xtf, uh, ul);

    // 3) W = U . G  (bf16 2-split, K=96)
    mma_gemm<1, 5, 0><<<dim3(2, 8, BNT), 256, smem_b>>>(
        uh, ul, sU, UK,  gh, gl, 0, UK,
        wwh, wwl, sWL, 128,  nullptr, 0, nullptr, UK);

    // 4) scores = W . U^T  (bf16 2-split, K=96, causal tile skip)
    mma_gemm<1, 0, 1><<<dim3(16, 8, BNT), 256, smem_b>>>(
        wwh, wwl, sWL, 128,  uh, ul, sU, UK,
        p, nullptr, sP, S,  nullptr, 0, nullptr, UK);

    // 5) softmax -> fp16 p (bperm)
    softmax_k<<<(BNT * S) / 8, 256>>>(p, ph);

    // 6) transpose t -> tT fp16 (bperm s)
    transpose_t_k<<<dim3(32, 8, BNT), 256>>>(t, tTh);

    // 7) att = p . t + t   (fp16 single, BK64, K limited)
    mma_gemm<0, 2, 2><<<dim3(4, 8, BNT), 256, smem_b>>>(
        ph, nullptr, sP, S,  tTh, nullptr, sT, S,
        att, nullptr, sT, DD,  t, sT, nullptr, S);

    // 8) hn = LN2(att) -> fp16 (bperm)
    ln_half_k<<<(BNT * S) / 8, 256>>>(att, hnh, ln2_g, ln2_b);

    // 9) hf = relu(hn . W1^T)  (fp16)
    mma_gemm<0, 1, 0><<<dim3(8, 8, BNT), 256, smem_b>>>(
        hnh, nullptr, sT, DD,  w1h, nullptr, 0, DD,
        hfh, nullptr, sH, FD,  nullptr, 0, nullptr, DD);

    // 10) y = hf . W2^T + t -> bf16 hi/lo (bperm)
    mma_gemm<0, 4, 0><<<dim3(4, 8, BNT), 256, smem_b>>>(
        hfh, nullptr, sH, FD,  w2h, nullptr, 0, FD,
        ybh, ybl, sT, DD,  t, sT, nullptr, FD);

    // 11) out = y . W_out^T (bf16 2-split, scatter epilogue)
    mma_gemm<1, 3, 0><<<dim3(1, 8, BNT), 256, smem_b>>>(
        ybh, ybl, sT, DD,  woh, wol, 0, DD,
        nullptr, nullptr, 0, 0,  nullptr, 0, out, DD);
}